// round 7
// baseline (speedup 1.0000x reference)
#include <cuda_runtime.h>
#include <cuda_fp16.h>
#include <cstdint>

// ---------------------------------------------------------------------------
// Problem constants
// ---------------------------------------------------------------------------
#define BROWS 4096
#define DDIM  4096
#define OROWS 4096
#define MBUCK 2048

#define GM 4096
#define GN 4096
#define GK 2048
#define BM 128
#define BN 128
#define BK 64
#define NKT (GK / BK)      // 32

#define A_TILE_B 16384
#define STAGE_B  32768
#define SMEM_TOTAL (2 * STAGE_B)

// ---------------------------------------------------------------------------
// Scratch
// ---------------------------------------------------------------------------
__device__ __align__(16) __half g_A[(size_t)GM * GK];  // 16 MB
__device__ __align__(16) __half g_B[(size_t)GN * GK];  // 16 MB
__device__ int      g_off[MBUCK + 1];
__device__ __align__(16) uint16_t g_perm[DDIM];   // bit15 = sign, bits0..11 = src index

// ---------------------------------------------------------------------------
// CSR build: counts -> scan -> perm (sign folded). One block.
// ---------------------------------------------------------------------------
__global__ __launch_bounds__(256) void build_csr(
    const int* __restrict__ hidx, const float* __restrict__ sgn)
{
    __shared__ int h[DDIM];
    __shared__ int cnt[MBUCK];
    __shared__ int offs[MBUCK + 1];
    __shared__ int psum[257];
    const int tid = threadIdx.x;

    for (int i = tid; i < DDIM; i += 256) h[i] = hidx[i];
    for (int i = tid; i < MBUCK; i += 256) cnt[i] = 0;
    __syncthreads();
    for (int i = tid; i < DDIM; i += 256) atomicAdd(&cnt[h[i]], 1);
    __syncthreads();

    int lc[8];
    {
        int local = 0;
        #pragma unroll
        for (int k = 0; k < 8; ++k) { lc[k] = local; local += cnt[tid * 8 + k]; }
        psum[tid] = local;
    }
    __syncthreads();
    if (tid == 0) {
        int run = 0;
        for (int t = 0; t < 256; ++t) { int v = psum[t]; psum[t] = run; run += v; }
        psum[256] = run;
    }
    __syncthreads();
    #pragma unroll
    for (int k = 0; k < 8; ++k) offs[tid * 8 + k] = psum[tid] + lc[k];
    if (tid == 0) offs[MBUCK] = psum[256];
    __syncthreads();

    for (int i = tid; i <= MBUCK; i += 256) g_off[i] = offs[i];
    for (int i = tid; i < MBUCK; i += 256) cnt[i] = offs[i];  // cursors
    __syncthreads();
    for (int i = tid; i < DDIM; i += 256) {
        int slot = atomicAdd(&cnt[h[i]], 1);
        uint16_t v = (uint16_t)i;
        if (sgn[i] < 0.0f) v |= 0x8000u;
        g_perm[slot] = v;
    }
}

// ---------------------------------------------------------------------------
// Sketch v2: gather-based, no atomics. 2 rows per block.
// blocks 0..2047 -> A rows, 2048..4095 -> B rows.
// out[j] = sum_{slots of bucket j} (+/-) x[perm_idx]
// ---------------------------------------------------------------------------
__global__ __launch_bounds__(256) void sketch_kernel(
    const float* __restrict__ inA, const float* __restrict__ inB)
{
    __shared__ __align__(16) float xs0[DDIM];
    __shared__ __align__(16) float xs1[DDIM];
    const int blk   = blockIdx.x;
    const int which = blk >> 11;
    const int row0  = (blk & 2047) * 2;
    const float* x  = which ? inB : inA;
    const int tid = threadIdx.x;

    const float4* r0 = (const float4*)(x + (size_t)row0 * DDIM);
    const float4* r1 = (const float4*)(x + (size_t)(row0 + 1) * DDIM);
    #pragma unroll
    for (int i = 0; i < 4; ++i) {
        ((float4*)xs0)[tid + i * 256] = r0[tid + i * 256];
        ((float4*)xs1)[tid + i * 256] = r1[tid + i * 256];
    }
    __syncthreads();

    const int j0 = tid * 8;
    int off_l[9];
    #pragma unroll
    for (int k = 0; k < 9; ++k) off_l[k] = __ldg(&g_off[j0 + k]);

    uint32_t out0[4], out1[4];
    #pragma unroll
    for (int kk = 0; kk < 4; ++kk) {
        float s0a = 0.f, s0b = 0.f, s1a = 0.f, s1b = 0.f;
        for (int s = off_l[2 * kk]; s < off_l[2 * kk + 1]; ++s) {
            const uint32_t p  = __ldg(&g_perm[s]);
            const uint32_t sx = (p & 0x8000u) << 16;
            const int i = p & 0xFFF;
            s0a += __uint_as_float(__float_as_uint(xs0[i]) ^ sx);
            s1a += __uint_as_float(__float_as_uint(xs1[i]) ^ sx);
        }
        for (int s = off_l[2 * kk + 1]; s < off_l[2 * kk + 2]; ++s) {
            const uint32_t p  = __ldg(&g_perm[s]);
            const uint32_t sx = (p & 0x8000u) << 16;
            const int i = p & 0xFFF;
            s0b += __uint_as_float(__float_as_uint(xs0[i]) ^ sx);
            s1b += __uint_as_float(__float_as_uint(xs1[i]) ^ sx);
        }
        __half2 h0 = __halves2half2(__float2half_rn(s0a), __float2half_rn(s0b));
        __half2 h1 = __halves2half2(__float2half_rn(s1a), __float2half_rn(s1b));
        out0[kk] = *(uint32_t*)&h0;
        out1[kk] = *(uint32_t*)&h1;
    }

    __half* pan = which ? g_B : g_A;
    *(uint4*)(pan + (size_t)row0 * GK + j0)       = make_uint4(out0[0], out0[1], out0[2], out0[3]);
    *(uint4*)(pan + (size_t)(row0 + 1) * GK + j0) = make_uint4(out1[0], out1[1], out1[2], out1[3]);
}

// ---------------------------------------------------------------------------
// GEMM helpers (unchanged from R6)
// ---------------------------------------------------------------------------
__device__ __forceinline__ uint32_t sm_u32(const void* p) {
    uint32_t r;
    asm("{ .reg .u64 t; cvta.to.shared.u64 t, %1; cvt.u32.u64 %0, t; }"
        : "=r"(r) : "l"(p));
    return r;
}

#define CP_ASYNC16(saddr, gaddr) \
    asm volatile("cp.async.cg.shared.global [%0], [%1], 16;" \
                 :: "r"(saddr), "l"(gaddr))
#define CP_COMMIT() asm volatile("cp.async.commit_group;")
#define CP_WAIT(n)  asm volatile("cp.async.wait_group %0;" :: "n"(n))

#define LDMATRIX_X4(r0, r1, r2, r3, addr) \
    asm volatile("ldmatrix.sync.aligned.m8n8.x4.shared.b16 {%0,%1,%2,%3}, [%4];" \
                 : "=r"(r0), "=r"(r1), "=r"(r2), "=r"(r3) : "r"(addr))

#define MMA_16816(d, a, b) \
    asm volatile("mma.sync.aligned.m16n8k16.row.col.f32.f16.f16.f32 " \
                 "{%0,%1,%2,%3}, {%4,%5,%6,%7}, {%8,%9}, {%0,%1,%2,%3};" \
                 : "+f"(d[0]), "+f"(d[1]), "+f"(d[2]), "+f"(d[3]) \
                 : "r"(a[0]), "r"(a[1]), "r"(a[2]), "r"(a[3]), \
                   "r"(b[0]), "r"(b[1]))

// ---------------------------------------------------------------------------
// GEMM-NT: C[4096,4096] = A[4096,2048] * B[4096,2048]^T + bias
// ---------------------------------------------------------------------------
__global__ __launch_bounds__(256, 2) void gemm_kernel(
    const float* __restrict__ bias,
    float* __restrict__ C)
{
    extern __shared__ char smem[];
    const uint32_t sb = sm_u32(smem);
    const int tid  = threadIdx.x;
    const int wid  = tid >> 5;
    const int lane = tid & 31;
    const int wm = wid >> 1;
    const int wn = wid & 1;
    const int bm = blockIdx.y * BM;
    const int bn = blockIdx.x * BN;

    const __half* gA = g_A + (size_t)bm * GK;
    const __half* gB = g_B + (size_t)bn * GK;

    const int lr = tid >> 3;
    const int lc = tid & 7;

    float acc[2][8][4];
    #pragma unroll
    for (int mi = 0; mi < 2; ++mi)
        #pragma unroll
        for (int ni = 0; ni < 8; ++ni)
            #pragma unroll
            for (int j = 0; j < 4; ++j) acc[mi][ni][j] = 0.0f;

    uint32_t s_store[2][4];
    #pragma unroll
    for (int p = 0; p < 4; ++p) {
        int r = p * 32 + lr;
        uint32_t off = (uint32_t)r * 128 + (uint32_t)((lc ^ (r & 7)) << 4);
        s_store[0][p] = sb + off;
        s_store[1][p] = sb + A_TILE_B + off;
    }

    const int a_row0 = wm * 32 + (lane & 15);
    const int a_kcb  = lane >> 4;
    const int b_n0   = wn * 64 + ((lane >> 4) << 3) + (lane & 7);
    const int b_kcb  = (lane >> 3) & 1;

    #define LOAD_STAGE(slot, k)                                                \
        do {                                                                   \
            const __half* ga = gA + (size_t)(k) * BK;                          \
            const __half* gb = gB + (size_t)(k) * BK;                          \
            const uint32_t so = (uint32_t)(slot) * STAGE_B;                    \
            _Pragma("unroll")                                                  \
            for (int p = 0; p < 4; ++p) {                                      \
                int r = p * 32 + lr;                                           \
                CP_ASYNC16(s_store[0][p] + so,                                 \
                           (uint64_t)(ga + (size_t)r * GK + lc * 8));          \
                CP_ASYNC16(s_store[1][p] + so,                                 \
                           (uint64_t)(gb + (size_t)r * GK + lc * 8));          \
            }                                                                  \
            CP_COMMIT();                                                       \
        } while (0)

    LOAD_STAGE(0, 0);

    for (int kt = 0; kt < NKT; ++kt) {
        const int s = kt & 1;
        if (kt + 1 < NKT) {
            LOAD_STAGE(s ^ 1, kt + 1);
            CP_WAIT(1);
        } else {
            CP_WAIT(0);
        }
        __syncthreads();

        const uint32_t sA = sb + (uint32_t)s * STAGE_B;
        const uint32_t sB = sA + A_TILE_B;

        #pragma unroll
        for (int k16 = 0; k16 < BK / 16; ++k16) {
            const int kc_a = k16 * 2 + a_kcb;
            const int kc_b = k16 * 2 + b_kcb;

            uint32_t a[2][4];
            #pragma unroll
            for (int mi = 0; mi < 2; ++mi) {
                int row = a_row0 + mi * 16;
                uint32_t addr = sA + (uint32_t)row * 128
                              + (uint32_t)((kc_a ^ (row & 7)) << 4);
                LDMATRIX_X4(a[mi][0], a[mi][1], a[mi][2], a[mi][3], addr);
            }
            uint32_t b[8][2];
            #pragma unroll
            for (int nj = 0; nj < 4; ++nj) {
                int n = b_n0 + nj * 16;
                uint32_t addr = sB + (uint32_t)n * 128
                              + (uint32_t)((kc_b ^ (n & 7)) << 4);
                LDMATRIX_X4(b[nj * 2][0], b[nj * 2][1],
                            b[nj * 2 + 1][0], b[nj * 2 + 1][1], addr);
            }
            #pragma unroll
            for (int mi = 0; mi < 2; ++mi)
                #pragma unroll
                for (int ni = 0; ni < 8; ++ni)
                    MMA_16816(acc[mi][ni], a[mi], b[ni]);
        }
        __syncthreads();
    }

    #pragma unroll
    for (int mi = 0; mi < 2; ++mi) {
        const int r0 = bm + wm * 32 + mi * 16 + (lane >> 2);
        #pragma unroll
        for (int ni = 0; ni < 8; ++ni) {
            const int col = bn + wn * 64 + ni * 8 + (lane & 3) * 2;
            const float b0 = __ldg(bias + col);
            const float b1 = __ldg(bias + col + 1);
            float2 v0 = make_float2(acc[mi][ni][0] + b0, acc[mi][ni][1] + b1);
            float2 v1 = make_float2(acc[mi][ni][2] + b0, acc[mi][ni][3] + b1);
            *(float2*)(C + (size_t)r0 * GN + col)       = v0;
            *(float2*)(C + (size_t)(r0 + 8) * GN + col) = v1;
        }
    }
}

// ---------------------------------------------------------------------------
// Launch
// ---------------------------------------------------------------------------
extern "C" void kernel_launch(void* const* d_in, const int* in_sizes, int n_in,
                              void* d_out, int out_size)
{
    const float* input  = (const float*)d_in[0];
    const float* weight = (const float*)d_in[1];
    const float* bias   = (const float*)d_in[2];
    const int*   hidx   = (const int*)d_in[3];
    const float* sgn    = (const float*)d_in[4];
    float* out = (float*)d_out;

    build_csr<<<1, 256>>>(hidx, sgn);
    sketch_kernel<<<4096, 256>>>(input, weight);

    cudaFuncSetAttribute(gemm_kernel,
                         cudaFuncAttributeMaxDynamicSharedMemorySize, SMEM_TOTAL);
    dim3 grid(GN / BN, GM / BM);  // 32 x 32
    gemm_kernel<<<grid, 256, SMEM_TOTAL>>>(bias, out);
}